// round 11
// baseline (speedup 1.0000x reference)
#include <cuda_runtime.h>
#include <cuda_bf16.h>
#include <cstdint>

#define NN   2048
#define DD   16
#define HH   64
#define G4   256
#define NCTA 128
#define ROWS 16
#define NTH  512
#define TKN  256          // nodes (k) per GEMM tile
#define NKT  (NN / TKN)   // 8 tiles

typedef unsigned long long u64;
typedef unsigned int u32;

// Global scratch (no cudaMalloc)
// q in mma-B-fragment order: u64 slot = {lo u32: pair-row pr, hi u32: pair-row pr+4},
// each u32 = {even-node bf16 lo, odd-node bf16 hi}. Index:
//   g_q64[p][ ((c*16 + w)*4 + r4)*64 + j ],  pr = 128c + 8w + r4 (+4 for hi half)
__device__ u64 g_q64[2][NKT * 16 * 4 * HH];       // 2 x 256KB
__device__ uint4 g_Afb[(size_t)NCTA * 4096];      // A bf16 mma-fragment order (8MB)
__device__ int g_bar = 0;                         // grid barrier (self-resetting)

struct Smem {
  float red[16][16][64];    // 64 KB  A@q k-split reduce
  float qred[4][16][64];    // 16 KB  q-phase k-split reduce
  float gs[16][256];        // 16 KB  gate redistribution
  float W_ih[DD][G4];       // 16 KB
  float W_hh[HH][G4];       // 64 KB
  float W_q [HH][HH];       // 16 KB
  float bias[G4];
  float b_q [HH];
  float W_d [HH];
  float hdup[HH][18][2];    // h duplicated {h,h}, transposed (9.2KB)
  float xdup[DD][18][2];    // x_t duplicated, transposed
};

__device__ __forceinline__ u32 bfpack(float lo, float hi) {   // {hi<<16 | lo}
  u32 r; asm("cvt.rn.bf16x2.f32 %0, %1, %2;" : "=r"(r) : "f"(hi), "f"(lo)); return r;
}
__device__ __forceinline__ void mma16(float* c, uint4 a, u32 b0, u32 b1) {
  asm volatile("mma.sync.aligned.m16n8k16.row.col.f32.bf16.bf16.f32 "
               "{%0,%1,%2,%3}, {%4,%5,%6,%7}, {%8,%9}, {%0,%1,%2,%3};"
               : "+f"(c[0]), "+f"(c[1]), "+f"(c[2]), "+f"(c[3])
               : "r"(a.x), "r"(a.y), "r"(a.z), "r"(a.w), "r"(b0), "r"(b1));
}
__device__ __forceinline__ void fma2(u64& d, u64 a, u64 b) {
  asm("fma.rn.f32x2 %0, %1, %2, %0;" : "+l"(d) : "l"(a), "l"(b));
}
__device__ __forceinline__ u64 pack2(float v) {
  u64 r; asm("mov.b64 %0, {%1, %1};" : "=l"(r) : "f"(v)); return r;
}
__device__ __forceinline__ float sigm_f(float x) { return 1.0f / (1.0f + __expf(-x)); }
__device__ __forceinline__ float tanh_f(float x) { return 1.0f - 2.0f / (__expf(2.0f * x) + 1.0f); }

__global__ void __launch_bounds__(NTH, 1)
rgcn_kernel(const float* __restrict__ x,    const float* __restrict__ A,
            const float* __restrict__ W_ih, const float* __restrict__ W_hh,
            const float* __restrict__ bias, const float* __restrict__ W_q,
            const float* __restrict__ b_q,  const float* __restrict__ W_d,
            const float* __restrict__ b_d,  float* __restrict__ out, int T)
{
  extern __shared__ unsigned char smem_raw[];
  Smem& s = *reinterpret_cast<Smem*>(smem_raw);

  const int tid = threadIdx.x, wid = tid >> 5, lane = tid & 31;
  const int n_base = blockIdx.x * ROWS;
  const int n   = n_base + wid;             // this warp's node row
  const int j0  = 2 * lane;
  const int rw4 = (wid >> 2) * 4;           // gates/q: 4-row group base
  const int cw  = wid & 3;                  // gates: 64-col block | q: k-slice
  const int gc0 = cw * 64 + j0;

  // ---- weights into shared ----
  for (int i = tid; i < DD * G4; i += NTH) (&s.W_ih[0][0])[i] = W_ih[i];
  for (int i = tid; i < HH * G4; i += NTH) (&s.W_hh[0][0])[i] = W_hh[i];
  for (int i = tid; i < HH * HH; i += NTH) (&s.W_q[0][0])[i]  = W_q[i];
  for (int i = tid; i < G4;      i += NTH) s.bias[i] = bias[i];
  for (int i = tid; i < HH;      i += NTH) { s.b_q[i] = b_q[i]; s.W_d[i] = W_d[i]; }
  for (int i = tid; i < HH * 18 * 2; i += NTH) (&s.hdup[0][0][0])[i] = 0.0f;

  // ---- one-time: pack this CTA's A rows into bf16 mma-fragment order ----
  for (int i = tid; i < 4096; i += NTH) {
    const int tile = i >> 9, w = (i >> 5) & 15, ln = i & 31;
    const int k0 = tile * TKN + (w << 4) + ((ln & 3) << 1);
    const int r = ln >> 2;
    const float* r0 = A + (size_t)(n_base + r) * NN;
    const float* r8 = A + (size_t)(n_base + r + 8) * NN;
    uint4 v;
    v.x = bfpack(__ldg(r0 + k0),     __ldg(r0 + k0 + 1));
    v.y = bfpack(__ldg(r8 + k0),     __ldg(r8 + k0 + 1));
    v.z = bfpack(__ldg(r0 + k0 + 8), __ldg(r0 + k0 + 9));
    v.w = bfpack(__ldg(r8 + k0 + 8), __ldg(r8 + k0 + 9));
    g_Afb[(size_t)blockIdx.x * 4096 + i] = v;
  }
  __syncthreads();
  const float bd = __ldg(b_d);
  const uint4* fragbase = g_Afb + (size_t)blockIdx.x * 4096 + wid * 32 + lane;

  // q writer address pieces (thread owns node n, cols j0/j0+1)
  const int cq  = n >> 8;                   // tile
  const int wq  = blockIdx.x & 15;          // slice within tile
  const int r8q = (n >> 1) & 7;
  const size_t qslot = (((size_t)cq * 16 + wq) * 4 + (r8q & 3)) * 64;  // u64 units
  const size_t qbyte = qslot * 8 + (size_t)(r8q >> 2) * 4 + (size_t)(n & 1) * 2;

  // GEMM B-fragment base (warp wid = k-slice), u64 units within a tile buffer
  const int bbase0 = wid * 256 + (lane & 3) * 64 + (lane >> 2);

  float c0r = 0.0f, c1r = 0.0f;    // cell state in registers

  for (int t = 0; t < T; ++t) {
    const int p = t & 1;

    // ===== stage x_t into duplicated-transposed smem =====
    if (tid < 256) {
      const int r = tid >> 4, d = tid & 15;
      const float xv = __ldg(&x[((size_t)(n_base + r) * T + t) * DD + d]);
      *reinterpret_cast<u64*>(&s.xdup[d][r][0]) = pack2(xv);
    }

    // ===== phase 1: q = tanh(h @ W_q + b_q); warp=(4 rows, k-slice cw*16) =====
    {
      u64 qacc[4] = {0ull, 0ull, 0ull, 0ull};
      #pragma unroll
      for (int kk = 0; kk < 16; ++kk) {
        const int k = (cw << 4) + kk;
        const u64 w2 = *reinterpret_cast<const u64*>(&s.W_q[k][j0]);
        const ulonglong2 h01 = *reinterpret_cast<const ulonglong2*>(&s.hdup[k][rw4][0]);
        const ulonglong2 h23 = *reinterpret_cast<const ulonglong2*>(&s.hdup[k][rw4 + 2][0]);
        fma2(qacc[0], h01.x, w2); fma2(qacc[1], h01.y, w2);
        fma2(qacc[2], h23.x, w2); fma2(qacc[3], h23.y, w2);
      }
      #pragma unroll
      for (int rr = 0; rr < 4; ++rr)
        *reinterpret_cast<u64*>(&s.qred[cw][rw4 + rr][j0]) = qacc[rr];
    }
    __syncthreads();                               // S1
    {
      float2 qs = make_float2(s.b_q[j0], s.b_q[j0 + 1]);
      #pragma unroll
      for (int kq = 0; kq < 4; ++kq) {
        const float2 v = *reinterpret_cast<const float2*>(&s.qred[kq][wid][j0]);
        qs.x += v.x; qs.y += v.y;
      }
      // publish q in fragment-ordered global layout (bf16 halfword stores)
      char* base = reinterpret_cast<char*>(&g_q64[p][0]) + qbyte;
      *reinterpret_cast<__nv_bfloat16*>(base + (size_t)j0 * 8)       = __float2bfloat16_rn(tanh_f(qs.x));
      *reinterpret_cast<__nv_bfloat16*>(base + (size_t)(j0 + 1) * 8) = __float2bfloat16_rn(tanh_f(qs.y));
    }

    // ===== barrier ARRIVE (release q writes) =====
    __threadfence();
    __syncthreads();                               // S2
    if (tid == 0) atomicAdd(&g_bar, 1);

    // ===== gates: warp=(4 rows rw4.., 64-col block cw); overlaps barrier skew =====
    {
      u64 accg[4];
      const u64 b2 = *reinterpret_cast<const u64*>(&s.bias[gc0]);
      accg[0] = b2; accg[1] = b2; accg[2] = b2; accg[3] = b2;
      #pragma unroll
      for (int d = 0; d < DD; ++d) {
        const u64 w2 = *reinterpret_cast<const u64*>(&s.W_ih[d][gc0]);
        const ulonglong2 x01 = *reinterpret_cast<const ulonglong2*>(&s.xdup[d][rw4][0]);
        const ulonglong2 x23 = *reinterpret_cast<const ulonglong2*>(&s.xdup[d][rw4 + 2][0]);
        fma2(accg[0], x01.x, w2); fma2(accg[1], x01.y, w2);
        fma2(accg[2], x23.x, w2); fma2(accg[3], x23.y, w2);
      }
      #pragma unroll 8
      for (int k = 0; k < HH; ++k) {
        const u64 w2 = *reinterpret_cast<const u64*>(&s.W_hh[k][gc0]);
        const ulonglong2 h01 = *reinterpret_cast<const ulonglong2*>(&s.hdup[k][rw4][0]);
        const ulonglong2 h23 = *reinterpret_cast<const ulonglong2*>(&s.hdup[k][rw4 + 2][0]);
        fma2(accg[0], h01.x, w2); fma2(accg[1], h01.y, w2);
        fma2(accg[2], h23.x, w2); fma2(accg[3], h23.y, w2);
      }
      // redistribute to row-major gate buffer now (read after S3 by act phase)
      #pragma unroll
      for (int rr = 0; rr < 4; ++rr)
        *reinterpret_cast<u64*>(&s.gs[rw4 + rr][gc0]) = accg[rr];
    }

    // ===== barrier WAIT (acquire all q) =====
    if (tid == 0) {
      const int target = NCTA * (t + 1);
      while (*((volatile int*)&g_bar) < target) { }
    }
    __syncthreads();                               // S3

    // ===== phase 2: D[16x64] = A_rows @ q, bf16 mma, B straight from L2 =====
    float acc[32];
    #pragma unroll
    for (int i = 0; i < 32; ++i) acc[i] = 0.0f;

    const u64* qb64 = &g_q64[p][0];
    uint4 frag = __ldg(fragbase);                  // tile 0 A-frag

    #pragma unroll 1
    for (int c = 0; c < NKT; ++c) {
      const u64* bp = qb64 + (size_t)c * 4096 + bbase0;
      u64 br[8];
      #pragma unroll
      for (int nc = 0; nc < 8; ++nc) br[nc] = __ldcg(bp + nc * 8);
      uint4 nfrag;
      if (c + 1 < NKT) nfrag = __ldg(fragbase + (c + 1) * 512);
      #pragma unroll
      for (int nc = 0; nc < 8; ++nc) {
        const u32 b0 = (u32)(br[nc] & 0xffffffffull);
        const u32 b1 = (u32)(br[nc] >> 32);
        mma16(acc + nc * 4, frag, b0, b1);
      }
      frag = nfrag;
    }

    // ===== reduce A@q k-split partials via smem =====
    {
      const int r = lane >> 2, cc = (lane & 3) * 2;
      #pragma unroll
      for (int nc = 0; nc < 8; ++nc) {
        *reinterpret_cast<float2*>(&s.red[wid][r][nc * 8 + cc]) =
            make_float2(acc[nc * 4 + 0], acc[nc * 4 + 1]);
        *reinterpret_cast<float2*>(&s.red[wid][r + 8][nc * 8 + cc]) =
            make_float2(acc[nc * 4 + 2], acc[nc * 4 + 3]);
      }
    }
    __syncthreads();                               // S4
    float2 aqv = make_float2(0.0f, 0.0f);
    #pragma unroll
    for (int w2 = 0; w2 < 16; ++w2) {
      const float2 v = *reinterpret_cast<const float2*>(&s.red[w2][wid][j0]);
      aqv.x += v.x; aqv.y += v.y;
    }

    // ===== activations + state update (warp wid owns row wid) =====
    {
      const float2 gi = *reinterpret_cast<const float2*>(&s.gs[wid][  0 + j0]);
      const float2 gf = *reinterpret_cast<const float2*>(&s.gs[wid][ 64 + j0]);
      const float2 gg = *reinterpret_cast<const float2*>(&s.gs[wid][128 + j0]);
      const float2 go = *reinterpret_cast<const float2*>(&s.gs[wid][192 + j0]);

      const float i0 = sigm_f(gi.x), i1 = sigm_f(gi.y);
      const float f0 = sigm_f(gf.x), f1 = sigm_f(gf.y);
      const float g0 = tanh_f(gg.x), g1 = tanh_f(gg.y);
      const float o0 = sigm_f(go.x), o1 = sigm_f(go.y);

      c0r = f0 * (c0r + aqv.x) + i0 * g0;
      c1r = f1 * (c1r + aqv.y) + i1 * g1;
      const float h0 = o0 * tanh_f(c0r);
      const float h1 = o1 * tanh_f(c1r);

      *reinterpret_cast<u64*>(&s.hdup[j0    ][wid][0]) = pack2(h0);
      *reinterpret_cast<u64*>(&s.hdup[j0 + 1][wid][0]) = pack2(h1);

      float part = h0 * s.W_d[j0] + h1 * s.W_d[j0 + 1];
      #pragma unroll
      for (int off = 16; off > 0; off >>= 1)
        part += __shfl_down_sync(0xffffffffu, part, off);
      if (lane == 0) out[(size_t)n * T + t] = part + bd;
    }
    __syncthreads();                               // S5 (hdup/gs/red safe for next step)
  }

  // ===== self-resetting barrier counter =====
  if (tid == 0) {
    const int ticket = atomicAdd(&g_bar, 1);
    if (ticket == NCTA * (T + 1) - 1) atomicExch(&g_bar, 0);
  }
}

extern "C" void kernel_launch(void* const* d_in, const int* in_sizes, int n_in,
                              void* d_out, int out_size) {
  const float* x    = (const float*)d_in[0];
  const float* A    = (const float*)d_in[1];
  const float* W_ih = (const float*)d_in[2];
  const float* W_hh = (const float*)d_in[3];
  const float* bias = (const float*)d_in[4];
  const float* W_q  = (const float*)d_in[5];
  const float* b_q  = (const float*)d_in[6];
  const float* W_d  = (const float*)d_in[7];
  const float* b_d  = (const float*)d_in[8];
  float* out = (float*)d_out;

  const int T = in_sizes[0] / (NN * DD);   // 365

  cudaFuncSetAttribute(rgcn_kernel, cudaFuncAttributeMaxDynamicSharedMemorySize,
                       (int)sizeof(Smem));
  rgcn_kernel<<<NCTA, NTH, sizeof(Smem)>>>(x, A, W_ih, W_hh, bias,
                                           W_q, b_q, W_d, b_d, out, T);
}

// round 12
// speedup vs baseline: 1.0827x; 1.0827x over previous
#include <cuda_runtime.h>
#include <cuda_bf16.h>
#include <cstdint>

#define NN   2048
#define DD   16
#define HH   64
#define G4   256
#define NCTA 128
#define ROWS 16
#define NTH  512
#define TKN  256          // nodes (k) per GEMM tile
#define NKT  (NN / TKN)   // 8 tiles
#define RP   72           // padded red row stride (floats): 2-way conflict floor

typedef unsigned long long u64;
typedef unsigned int u32;

// q in mma-B-fragment order: u64 slot = {lo u32: pair-row pr, hi u32: pair-row pr+4},
// each u32 = {even-node bf16 lo, odd-node bf16 hi}.
//   g_q64[p][ ((c*16 + w)*4 + r4)*64 + j ]  ==  blockIdx-local: blk*256 + r4*64 + j
__device__ u64 g_q64[2][NKT * 16 * 4 * HH];       // 2 x 256KB
__device__ uint4 g_Afb[(size_t)NCTA * 4096];      // A bf16 mma-fragment order (8MB)
__device__ int g_bar = 0;                         // grid barrier (self-resetting)

struct Smem {
  float red[16][16][RP];    // 73.7 KB  A@q k-split reduce (padded rows)
  float qred[4][16][64];    // 16 KB  q-phase k-split reduce
  float qfin[16][64];       // 4 KB   final q (f32) before packed publish
  float gs[16][256];        // 16 KB  gate redistribution
  float W_ih[DD][G4];       // 16 KB
  float W_hh[HH][G4];       // 64 KB
  float W_q [HH][HH];       // 16 KB
  float bias[G4];
  float b_q [HH];
  float W_d [HH];
  float hdup[HH][18][2];    // h duplicated {h,h}, transposed (9.2KB)
  float xdup[DD][18][2];    // x_t duplicated, transposed
};

__device__ __forceinline__ u32 bfpack(float lo, float hi) {   // {hi<<16 | lo}
  u32 r; asm("cvt.rn.bf16x2.f32 %0, %1, %2;" : "=r"(r) : "f"(hi), "f"(lo)); return r;
}
__device__ __forceinline__ void mma16(float* c, uint4 a, u32 b0, u32 b1) {
  asm volatile("mma.sync.aligned.m16n8k16.row.col.f32.bf16.bf16.f32 "
               "{%0,%1,%2,%3}, {%4,%5,%6,%7}, {%8,%9}, {%0,%1,%2,%3};"
               : "+f"(c[0]), "+f"(c[1]), "+f"(c[2]), "+f"(c[3])
               : "r"(a.x), "r"(a.y), "r"(a.z), "r"(a.w), "r"(b0), "r"(b1));
}
__device__ __forceinline__ void fma2(u64& d, u64 a, u64 b) {
  asm("fma.rn.f32x2 %0, %1, %2, %0;" : "+l"(d) : "l"(a), "l"(b));
}
__device__ __forceinline__ u64 pack2(float v) {
  u64 r; asm("mov.b64 %0, {%1, %1};" : "=l"(r) : "f"(v)); return r;
}
__device__ __forceinline__ float sigm_f(float x) { return 1.0f / (1.0f + __expf(-x)); }
__device__ __forceinline__ float tanh_f(float x) { return 1.0f - 2.0f / (__expf(2.0f * x) + 1.0f); }

__global__ void __launch_bounds__(NTH, 1)
rgcn_kernel(const float* __restrict__ x,    const float* __restrict__ A,
            const float* __restrict__ W_ih, const float* __restrict__ W_hh,
            const float* __restrict__ bias, const float* __restrict__ W_q,
            const float* __restrict__ b_q,  const float* __restrict__ W_d,
            const float* __restrict__ b_d,  float* __restrict__ out, int T)
{
  extern __shared__ unsigned char smem_raw[];
  Smem& s = *reinterpret_cast<Smem*>(smem_raw);

  const int tid = threadIdx.x, wid = tid >> 5, lane = tid & 31;
  const int n_base = blockIdx.x * ROWS;
  const int n   = n_base + wid;             // this warp's node row
  const int j0  = 2 * lane;
  const int rw4 = (wid >> 2) * 4;           // gates/q: 4-row group base
  const int cw  = wid & 3;                  // gates: 64-col block | q: k-slice
  const int gc0 = cw * 64 + j0;

  // ---- weights into shared ----
  for (int i = tid; i < DD * G4; i += NTH) (&s.W_ih[0][0])[i] = W_ih[i];
  for (int i = tid; i < HH * G4; i += NTH) (&s.W_hh[0][0])[i] = W_hh[i];
  for (int i = tid; i < HH * HH; i += NTH) (&s.W_q[0][0])[i]  = W_q[i];
  for (int i = tid; i < G4;      i += NTH) s.bias[i] = bias[i];
  for (int i = tid; i < HH;      i += NTH) { s.b_q[i] = b_q[i]; s.W_d[i] = W_d[i]; }
  for (int i = tid; i < HH * 18 * 2; i += NTH) (&s.hdup[0][0][0])[i] = 0.0f;

  // ---- one-time: pack this CTA's A rows into bf16 mma-fragment order ----
  for (int i = tid; i < 4096; i += NTH) {
    const int tile = i >> 9, w = (i >> 5) & 15, ln = i & 31;
    const int k0 = tile * TKN + (w << 4) + ((ln & 3) << 1);
    const int r = ln >> 2;
    const float* r0 = A + (size_t)(n_base + r) * NN;
    const float* r8 = A + (size_t)(n_base + r + 8) * NN;
    uint4 v;
    v.x = bfpack(__ldg(r0 + k0),     __ldg(r0 + k0 + 1));
    v.y = bfpack(__ldg(r8 + k0),     __ldg(r8 + k0 + 1));
    v.z = bfpack(__ldg(r0 + k0 + 8), __ldg(r0 + k0 + 9));
    v.w = bfpack(__ldg(r8 + k0 + 8), __ldg(r8 + k0 + 9));
    g_Afb[(size_t)blockIdx.x * 4096 + i] = v;
  }
  __syncthreads();
  const float bd = __ldg(b_d);
  const uint4* fragbase = g_Afb + (size_t)blockIdx.x * 4096 + wid * 32 + lane;

  // q publish (coalesced): tid<256 -> (r4 = tid>>6, j = tid&63)
  const int pr4 = tid >> 6, pj = tid & 63;
  u64* qdst0 = &g_q64[0][(size_t)blockIdx.x * 256 + pr4 * 64 + pj];
  u64* qdst1 = &g_q64[1][(size_t)blockIdx.x * 256 + pr4 * 64 + pj];

  // GEMM B-fragment base (warp wid = k-slice), u64 units within a tile buffer
  const int bbase0 = wid * 256 + (lane & 3) * 64 + (lane >> 2);

  float c0r = 0.0f, c1r = 0.0f;    // cell state in registers

  for (int t = 0; t < T; ++t) {
    const int p = t & 1;

    // ===== stage x_t into duplicated-transposed smem =====
    if (tid < 256) {
      const int r = tid >> 4, d = tid & 15;
      const float xv = __ldg(&x[((size_t)(n_base + r) * T + t) * DD + d]);
      *reinterpret_cast<u64*>(&s.xdup[d][r][0]) = pack2(xv);
    }

    // ===== phase 1: q = tanh(h @ W_q + b_q); warp=(4 rows, k-slice cw*16) =====
    {
      u64 qacc[4] = {0ull, 0ull, 0ull, 0ull};
      #pragma unroll
      for (int kk = 0; kk < 16; ++kk) {
        const int k = (cw << 4) + kk;
        const u64 w2 = *reinterpret_cast<const u64*>(&s.W_q[k][j0]);
        const ulonglong2 h01 = *reinterpret_cast<const ulonglong2*>(&s.hdup[k][rw4][0]);
        const ulonglong2 h23 = *reinterpret_cast<const ulonglong2*>(&s.hdup[k][rw4 + 2][0]);
        fma2(qacc[0], h01.x, w2); fma2(qacc[1], h01.y, w2);
        fma2(qacc[2], h23.x, w2); fma2(qacc[3], h23.y, w2);
      }
      #pragma unroll
      for (int rr = 0; rr < 4; ++rr)
        *reinterpret_cast<u64*>(&s.qred[cw][rw4 + rr][j0]) = qacc[rr];
    }
    __syncthreads();                               // S1
    {
      float2 qs = make_float2(s.b_q[j0], s.b_q[j0 + 1]);
      #pragma unroll
      for (int kq = 0; kq < 4; ++kq) {
        const float2 v = *reinterpret_cast<const float2*>(&s.qred[kq][wid][j0]);
        qs.x += v.x; qs.y += v.y;
      }
      s.qfin[wid][j0]     = tanh_f(qs.x);
      s.qfin[wid][j0 + 1] = tanh_f(qs.y);
    }
    __syncthreads();                               // S1b
    // ===== publish q: packed u64 fragment slots, fully coalesced =====
    if (tid < 256) {
      const u32 lo = bfpack(s.qfin[2 * pr4][pj],     s.qfin[2 * pr4 + 1][pj]);
      const u32 hi = bfpack(s.qfin[2 * pr4 + 8][pj], s.qfin[2 * pr4 + 9][pj]);
      *(p ? qdst1 : qdst0) = (u64)lo | ((u64)hi << 32);
    }

    // ===== barrier ARRIVE (release q writes) =====
    __threadfence();
    __syncthreads();                               // S2
    if (tid == 0) atomicAdd(&g_bar, 1);

    // ===== gates: warp=(4 rows rw4.., 64-col block cw); overlaps barrier skew =====
    {
      u64 accg[4];
      const u64 b2 = *reinterpret_cast<const u64*>(&s.bias[gc0]);
      accg[0] = b2; accg[1] = b2; accg[2] = b2; accg[3] = b2;
      #pragma unroll
      for (int d = 0; d < DD; ++d) {
        const u64 w2 = *reinterpret_cast<const u64*>(&s.W_ih[d][gc0]);
        const ulonglong2 x01 = *reinterpret_cast<const ulonglong2*>(&s.xdup[d][rw4][0]);
        const ulonglong2 x23 = *reinterpret_cast<const ulonglong2*>(&s.xdup[d][rw4 + 2][0]);
        fma2(accg[0], x01.x, w2); fma2(accg[1], x01.y, w2);
        fma2(accg[2], x23.x, w2); fma2(accg[3], x23.y, w2);
      }
      #pragma unroll 8
      for (int k = 0; k < HH; ++k) {
        const u64 w2 = *reinterpret_cast<const u64*>(&s.W_hh[k][gc0]);
        const ulonglong2 h01 = *reinterpret_cast<const ulonglong2*>(&s.hdup[k][rw4][0]);
        const ulonglong2 h23 = *reinterpret_cast<const ulonglong2*>(&s.hdup[k][rw4 + 2][0]);
        fma2(accg[0], h01.x, w2); fma2(accg[1], h01.y, w2);
        fma2(accg[2], h23.x, w2); fma2(accg[3], h23.y, w2);
      }
      #pragma unroll
      for (int rr = 0; rr < 4; ++rr)
        *reinterpret_cast<u64*>(&s.gs[rw4 + rr][gc0]) = accg[rr];
    }

    // prefetch tile-0 A-fragment (constant data; hides L2 latency behind spin)
    uint4 frag = __ldg(fragbase);

    // ===== barrier WAIT (acquire all q) =====
    if (tid == 0) {
      const int target = NCTA * (t + 1);
      while (*((volatile int*)&g_bar) < target) { }
    }
    __syncthreads();                               // S3

    // ===== phase 2: D[16x64] = A_rows @ q, bf16 mma, B straight from L2 =====
    float acc[32];
    #pragma unroll
    for (int i = 0; i < 32; ++i) acc[i] = 0.0f;

    const u64* qb64 = &g_q64[p][0];

    #pragma unroll 1
    for (int c = 0; c < NKT; ++c) {
      const u64* bp = qb64 + (size_t)c * 4096 + bbase0;
      u64 br[8];
      #pragma unroll
      for (int nc = 0; nc < 8; ++nc) br[nc] = __ldcg(bp + nc * 8);
      uint4 nfrag;
      if (c + 1 < NKT) nfrag = __ldg(fragbase + (c + 1) * 512);
      #pragma unroll
      for (int nc = 0; nc < 8; ++nc) {
        const u32 b0 = (u32)(br[nc] & 0xffffffffull);
        const u32 b1 = (u32)(br[nc] >> 32);
        mma16(acc + nc * 4, frag, b0, b1);
      }
      frag = nfrag;
    }

    // ===== reduce A@q k-split partials via smem (padded rows: 2-way max) =====
    {
      const int r = lane >> 2, cc = (lane & 3) * 2;
      #pragma unroll
      for (int nc = 0; nc < 8; ++nc) {
        *reinterpret_cast<float2*>(&s.red[wid][r][nc * 8 + cc]) =
            make_float2(acc[nc * 4 + 0], acc[nc * 4 + 1]);
        *reinterpret_cast<float2*>(&s.red[wid][r + 8][nc * 8 + cc]) =
            make_float2(acc[nc * 4 + 2], acc[nc * 4 + 3]);
      }
    }
    __syncthreads();                               // S4
    float2 aqv = make_float2(0.0f, 0.0f);
    #pragma unroll
    for (int w2 = 0; w2 < 16; ++w2) {
      const float2 v = *reinterpret_cast<const float2*>(&s.red[w2][wid][j0]);
      aqv.x += v.x; aqv.y += v.y;
    }

    // ===== activations + state update (warp wid owns row wid) =====
    {
      const float2 gi = *reinterpret_cast<const float2*>(&s.gs[wid][  0 + j0]);
      const float2 gf = *reinterpret_cast<const float2*>(&s.gs[wid][ 64 + j0]);
      const float2 gg = *reinterpret_cast<const float2*>(&s.gs[wid][128 + j0]);
      const float2 go = *reinterpret_cast<const float2*>(&s.gs[wid][192 + j0]);

      const float i0 = sigm_f(gi.x), i1 = sigm_f(gi.y);
      const float f0 = sigm_f(gf.x), f1 = sigm_f(gf.y);
      const float g0 = tanh_f(gg.x), g1 = tanh_f(gg.y);
      const float o0 = sigm_f(go.x), o1 = sigm_f(go.y);

      c0r = f0 * (c0r + aqv.x) + i0 * g0;
      c1r = f1 * (c1r + aqv.y) + i1 * g1;
      const float h0 = o0 * tanh_f(c0r);
      const float h1 = o1 * tanh_f(c1r);

      *reinterpret_cast<u64*>(&s.hdup[j0    ][wid][0]) = pack2(h0);
      *reinterpret_cast<u64*>(&s.hdup[j0 + 1][wid][0]) = pack2(h1);

      float part = h0 * s.W_d[j0] + h1 * s.W_d[j0 + 1];
      #pragma unroll
      for (int off = 16; off > 0; off >>= 1)
        part += __shfl_down_sync(0xffffffffu, part, off);
      if (lane == 0) out[(size_t)n * T + t] = part + bd;
    }
    __syncthreads();                               // S5
  }

  // ===== self-resetting barrier counter =====
  if (tid == 0) {
    const int ticket = atomicAdd(&g_bar, 1);
    if (ticket == NCTA * (T + 1) - 1) atomicExch(&g_bar, 0);
  }
}

extern "C" void kernel_launch(void* const* d_in, const int* in_sizes, int n_in,
                              void* d_out, int out_size) {
  const float* x    = (const float*)d_in[0];
  const float* A    = (const float*)d_in[1];
  const float* W_ih = (const float*)d_in[2];
  const float* W_hh = (const float*)d_in[3];
  const float* bias = (const float*)d_in[4];
  const float* W_q  = (const float*)d_in[5];
  const float* b_q  = (const float*)d_in[6];
  const float* W_d  = (const float*)d_in[7];
  const float* b_d  = (const float*)d_in[8];
  float* out = (float*)d_out;

  const int T = in_sizes[0] / (NN * DD);   // 365

  cudaFuncSetAttribute(rgcn_kernel, cudaFuncAttributeMaxDynamicSharedMemorySize,
                       (int)sizeof(Smem));
  rgcn_kernel<<<NCTA, NTH, sizeof(Smem)>>>(x, A, W_ih, W_hh, bias,
                                           W_q, b_q, W_d, b_d, out, T);
}

// round 15
// speedup vs baseline: 1.0837x; 1.0009x over previous
#include <cuda_runtime.h>
#include <cuda_bf16.h>
#include <cstdint>

#define NN   2048
#define DD   16
#define HH   64
#define G4   256
#define NCTA 128
#define ROWS 16
#define NTH  512
#define TKN  256          // nodes (k) per GEMM tile
#define NKT  (NN / TKN)   // 8 tiles
#define RP   72           // padded red row stride (floats): 2-way conflict floor

typedef unsigned long long u64;
typedef unsigned int u32;

// q in mma-B-fragment order: u64 slot = {lo u32: pair-row pr, hi u32: pair-row pr+4},
// each u32 = {even-node bf16 lo, odd-node bf16 hi}.
__device__ u64 g_q64[2][NKT * 16 * 4 * HH];       // 2 x 256KB
__device__ uint4 g_Afb[(size_t)NCTA * 4096];      // A bf16 mma-fragment order (8MB)
__device__ int g_bar = 0;                         // grid barrier (self-resetting)

struct Smem {
  float red[16][16][RP];    // 73.7 KB  A@q k-split reduce (padded rows)
  float qred[4][16][64];    // 16 KB  q-phase k-split reduce
  float qfin[16][64];       // 4 KB   final q (f32) before packed publish
  float gs[16][256];        // 16 KB  gate redistribution
  float W_ih[DD][G4];       // 16 KB
  float W_hh[HH][G4];       // 64 KB
  float W_q [HH][HH];       // 16 KB
  float bias[G4];
  float b_q [HH];
  float W_d [HH];
  float hdup[HH][18][2];    // h duplicated {h,h}, transposed (9.2KB)
  float xdup[DD][18][2];    // x_t duplicated, transposed
};

__device__ __forceinline__ u32 bfpack(float lo, float hi) {   // {hi<<16 | lo}
  u32 r; asm("cvt.rn.bf16x2.f32 %0, %1, %2;" : "=r"(r) : "f"(hi), "f"(lo)); return r;
}
__device__ __forceinline__ void mma16(float* c, uint4 a, u32 b0, u32 b1) {
  asm volatile("mma.sync.aligned.m16n8k16.row.col.f32.bf16.bf16.f32 "
               "{%0,%1,%2,%3}, {%4,%5,%6,%7}, {%8,%9}, {%0,%1,%2,%3};"
               : "+f"(c[0]), "+f"(c[1]), "+f"(c[2]), "+f"(c[3])
               : "r"(a.x), "r"(a.y), "r"(a.z), "r"(a.w), "r"(b0), "r"(b1));
}
__device__ __forceinline__ void fma2(u64& d, u64 a, u64 b) {
  asm("fma.rn.f32x2 %0, %1, %2, %0;" : "+l"(d) : "l"(a), "l"(b));
}
__device__ __forceinline__ u64 pack2(float v) {
  u64 r; asm("mov.b64 %0, {%1, %1};" : "=l"(r) : "f"(v)); return r;
}
__device__ __forceinline__ float sigm_f(float x) { return 1.0f / (1.0f + __expf(-x)); }
__device__ __forceinline__ float tanh_f(float x) { return 1.0f - 2.0f / (__expf(2.0f * x) + 1.0f); }

__global__ void __launch_bounds__(NTH, 1)
rgcn_kernel(const float* __restrict__ x,    const float* __restrict__ A,
            const float* __restrict__ W_ih, const float* __restrict__ W_hh,
            const float* __restrict__ bias, const float* __restrict__ W_q,
            const float* __restrict__ b_q,  const float* __restrict__ W_d,
            const float* __restrict__ b_d,  float* __restrict__ out, int T)
{
  extern __shared__ unsigned char smem_raw[];
  Smem& s = *reinterpret_cast<Smem*>(smem_raw);

  const int tid = threadIdx.x, wid = tid >> 5, lane = tid & 31;
  const int n_base = blockIdx.x * ROWS;
  const int n   = n_base + wid;             // this warp's node row
  const int j0  = 2 * lane;
  const int rw4 = (wid >> 2) * 4;           // gates/q: 4-row group base
  const int cw  = wid & 3;                  // gates: 64-col block | q: k-slice
  const int gc0 = cw * 64 + j0;

  // ---- weights into shared ----
  for (int i = tid; i < DD * G4; i += NTH) (&s.W_ih[0][0])[i] = W_ih[i];
  for (int i = tid; i < HH * G4; i += NTH) (&s.W_hh[0][0])[i] = W_hh[i];
  for (int i = tid; i < HH * HH; i += NTH) (&s.W_q[0][0])[i]  = W_q[i];
  for (int i = tid; i < G4;      i += NTH) s.bias[i] = bias[i];
  for (int i = tid; i < HH;      i += NTH) { s.b_q[i] = b_q[i]; s.W_d[i] = W_d[i]; }
  for (int i = tid; i < HH * 18 * 2; i += NTH) (&s.hdup[0][0][0])[i] = 0.0f;

  // ---- one-time: pack this CTA's A rows into bf16 mma-fragment order ----
  for (int i = tid; i < 4096; i += NTH) {
    const int tile = i >> 9, w = (i >> 5) & 15, ln = i & 31;
    const int k0 = tile * TKN + (w << 4) + ((ln & 3) << 1);
    const int r = ln >> 2;
    const float* r0 = A + (size_t)(n_base + r) * NN;
    const float* r8 = A + (size_t)(n_base + r + 8) * NN;
    uint4 v;
    v.x = bfpack(__ldg(r0 + k0),     __ldg(r0 + k0 + 1));
    v.y = bfpack(__ldg(r8 + k0),     __ldg(r8 + k0 + 1));
    v.z = bfpack(__ldg(r0 + k0 + 8), __ldg(r0 + k0 + 9));
    v.w = bfpack(__ldg(r8 + k0 + 8), __ldg(r8 + k0 + 9));
    g_Afb[(size_t)blockIdx.x * 4096 + i] = v;
  }
  __syncthreads();
  const float bd = __ldg(b_d);
  const uint4* fragbase = g_Afb + (size_t)blockIdx.x * 4096 + wid * 32 + lane;

  // q publish (coalesced): tid<256 -> (r4 = tid>>6, j = tid&63)
  const int pr4 = tid >> 6, pj = tid & 63;
  u64* qdst0 = &g_q64[0][(size_t)blockIdx.x * 256 + pr4 * 64 + pj];
  u64* qdst1 = &g_q64[1][(size_t)blockIdx.x * 256 + pr4 * 64 + pj];

  // GEMM B-fragment base (warp wid = k-slice), u64 units within a tile buffer
  const int bbase0 = wid * 256 + (lane & 3) * 64 + (lane >> 2);

  float c0r = 0.0f, c1r = 0.0f;    // cell state in registers

  for (int t = 0; t < T; ++t) {
    const int p = t & 1;

    // ===== stage x_t into duplicated-transposed smem =====
    if (tid < 256) {
      const int r = tid >> 4, d = tid & 15;
      const float xv = __ldg(&x[((size_t)(n_base + r) * T + t) * DD + d]);
      *reinterpret_cast<u64*>(&s.xdup[d][r][0]) = pack2(xv);
    }

    // ===== phase 1: q = tanh(h @ W_q + b_q); warp=(4 rows, k-slice cw*16) =====
    {
      u64 qacc[4] = {0ull, 0ull, 0ull, 0ull};
      #pragma unroll
      for (int kk = 0; kk < 16; ++kk) {
        const int k = (cw << 4) + kk;
        const u64 w2 = *reinterpret_cast<const u64*>(&s.W_q[k][j0]);
        const ulonglong2 h01 = *reinterpret_cast<const ulonglong2*>(&s.hdup[k][rw4][0]);
        const ulonglong2 h23 = *reinterpret_cast<const ulonglong2*>(&s.hdup[k][rw4 + 2][0]);
        fma2(qacc[0], h01.x, w2); fma2(qacc[1], h01.y, w2);
        fma2(qacc[2], h23.x, w2); fma2(qacc[3], h23.y, w2);
      }
      #pragma unroll
      for (int rr = 0; rr < 4; ++rr)
        *reinterpret_cast<u64*>(&s.qred[cw][rw4 + rr][j0]) = qacc[rr];
    }
    __syncthreads();                               // S1
    {
      float2 qs = make_float2(s.b_q[j0], s.b_q[j0 + 1]);
      #pragma unroll
      for (int kq = 0; kq < 4; ++kq) {
        const float2 v = *reinterpret_cast<const float2*>(&s.qred[kq][wid][j0]);
        qs.x += v.x; qs.y += v.y;
      }
      s.qfin[wid][j0]     = tanh_f(qs.x);
      s.qfin[wid][j0 + 1] = tanh_f(qs.y);
    }
    __syncthreads();                               // S1b
    // ===== publish q: packed u64 fragment slots, fully coalesced =====
    if (tid < 256) {
      const u32 lo = bfpack(s.qfin[2 * pr4][pj],     s.qfin[2 * pr4 + 1][pj]);
      const u32 hi = bfpack(s.qfin[2 * pr4 + 8][pj], s.qfin[2 * pr4 + 9][pj]);
      *(p ? qdst1 : qdst0) = (u64)lo | ((u64)hi << 32);
      __threadfence();             // only the storing warps pay the membar
    }

    // ===== barrier ARRIVE (release q writes) =====
    __syncthreads();                               // S2
    if (tid == 0) atomicAdd(&g_bar, 1);

    // ===== gates: warp=(4 rows rw4.., 64-col block cw); overlaps barrier skew =====
    {
      u64 accg[4];
      const u64 b2 = *reinterpret_cast<const u64*>(&s.bias[gc0]);
      accg[0] = b2; accg[1] = b2; accg[2] = b2; accg[3] = b2;
      #pragma unroll
      for (int d = 0; d < DD; ++d) {
        const u64 w2 = *reinterpret_cast<const u64*>(&s.W_ih[d][gc0]);
        const ulonglong2 x01 = *reinterpret_cast<const ulonglong2*>(&s.xdup[d][rw4][0]);
        const ulonglong2 x23 = *reinterpret_cast<const ulonglong2*>(&s.xdup[d][rw4 + 2][0]);
        fma2(accg[0], x01.x, w2); fma2(accg[1], x01.y, w2);
        fma2(accg[2], x23.x, w2); fma2(accg[3], x23.y, w2);
      }
      #pragma unroll 8
      for (int k = 0; k < HH; ++k) {
        const u64 w2 = *reinterpret_cast<const u64*>(&s.W_hh[k][gc0]);
        const ulonglong2 h01 = *reinterpret_cast<const ulonglong2*>(&s.hdup[k][rw4][0]);
        const ulonglong2 h23 = *reinterpret_cast<const ulonglong2*>(&s.hdup[k][rw4 + 2][0]);
        fma2(accg[0], h01.x, w2); fma2(accg[1], h01.y, w2);
        fma2(accg[2], h23.x, w2); fma2(accg[3], h23.y, w2);
      }
      #pragma unroll
      for (int rr = 0; rr < 4; ++rr)
        *reinterpret_cast<u64*>(&s.gs[rw4 + rr][gc0]) = accg[rr];
    }

    // prefetch A-fragments for tiles 0/1 (constant data; hides behind spin)
    uint4 fr0 = __ldg(fragbase);
    uint4 fr1 = __ldg(fragbase + 512);

    // ===== barrier WAIT (acquire all q) =====
    if (tid == 0) {
      const int target = NCTA * (t + 1);
      while (*((volatile int*)&g_bar) < target) { }
    }
    __syncthreads();                               // S3

    // ===== phase 2: D[16x64] = A_rows @ q, bf16 mma, reg-double-buffered =====
    float acc[32];
    #pragma unroll
    for (int i = 0; i < 32; ++i) acc[i] = 0.0f;

    const u64* qb64 = &g_q64[p][0];
    u64 br0[8], br1[8];
    {
      const u64* bp0 = qb64 + bbase0;
      const u64* bp1 = qb64 + 4096 + bbase0;
      #pragma unroll
      for (int nc = 0; nc < 8; ++nc) br0[nc] = __ldcg(bp0 + nc * 8);
      #pragma unroll
      for (int nc = 0; nc < 8; ++nc) br1[nc] = __ldcg(bp1 + nc * 8);
    }

    #pragma unroll 1
    for (int cc = 0; cc < NKT / 2; ++cc) {
      // --- even tile c = 2cc ---
      {
        u64 cur[8];
        #pragma unroll
        for (int nc = 0; nc < 8; ++nc) cur[nc] = br0[nc];
        const uint4 cf = fr0;
        if (cc < NKT / 2 - 1) {                    // prefetch tile 2cc+2
          const u64* bp = qb64 + (size_t)(2 * cc + 2) * 4096 + bbase0;
          #pragma unroll
          for (int nc = 0; nc < 8; ++nc) br0[nc] = __ldcg(bp + nc * 8);
          fr0 = __ldg(fragbase + (2 * cc + 2) * 512);
        }
        #pragma unroll
        for (int nc = 0; nc < 8; ++nc)
          mma16(acc + nc * 4, cf, (u32)(cur[nc] & 0xffffffffull), (u32)(cur[nc] >> 32));
      }
      // --- odd tile c = 2cc+1 ---
      {
        u64 cur[8];
        #pragma unroll
        for (int nc = 0; nc < 8; ++nc) cur[nc] = br1[nc];
        const uint4 cf = fr1;
        if (cc < NKT / 2 - 1) {                    // prefetch tile 2cc+3
          const u64* bp = qb64 + (size_t)(2 * cc + 3) * 4096 + bbase0;
          #pragma unroll
          for (int nc = 0; nc < 8; ++nc) br1[nc] = __ldcg(bp + nc * 8);
          fr1 = __ldg(fragbase + (2 * cc + 3) * 512);
        }
        #pragma unroll
        for (int nc = 0; nc < 8; ++nc)
          mma16(acc + nc * 4, cf, (u32)(cur[nc] & 0xffffffffull), (u32)(cur[nc] >> 32));
      }
    }

    // ===== reduce A@q k-split partials via smem (padded rows: 2-way max) =====
    {
      const int r = lane >> 2, cc2 = (lane & 3) * 2;
      #pragma unroll
      for (int nc = 0; nc < 8; ++nc) {
        *reinterpret_cast<float2*>(&s.red[wid][r][nc * 8 + cc2]) =
            make_float2(acc[nc * 4 + 0], acc[nc * 4 + 1]);
        *reinterpret_cast<float2*>(&s.red[wid][r + 8][nc * 8 + cc2]) =
            make_float2(acc[nc * 4 + 2], acc[nc * 4 + 3]);
      }
    }
    __syncthreads();                               // S4
    float2 aqv = make_float2(0.0f, 0.0f);
    #pragma unroll
    for (int w2 = 0; w2 < 16; ++w2) {
      const float2 v = *reinterpret_cast<const float2*>(&s.red[w2][wid][j0]);
      aqv.x += v.x; aqv.y += v.y;
    }

    // ===== activations + state update (warp wid owns row wid) =====
    {
      const float2 gi = *reinterpret_cast<const float2*>(&s.gs[wid][  0 + j0]);
      const float2 gf = *reinterpret_cast<const float2*>(&s.gs[wid][ 64 + j0]);
      const float2 gg = *reinterpret_cast<const float2*>(&s.gs[wid][128 + j0]);
      const float2 go = *reinterpret_cast<const float2*>(&s.gs[wid][192 + j0]);

      const float i0 = sigm_f(gi.x), i1 = sigm_f(gi.y);
      const float f0 = sigm_f(gf.x), f1 = sigm_f(gf.y);
      const float g0 = tanh_f(gg.x), g1 = tanh_f(gg.y);
      const float o0 = sigm_f(go.x), o1 = sigm_f(go.y);

      c0r = f0 * (c0r + aqv.x) + i0 * g0;
      c1r = f1 * (c1r + aqv.y) + i1 * g1;
      const float h0 = o0 * tanh_f(c0r);
      const float h1 = o1 * tanh_f(c1r);

      *reinterpret_cast<u64*>(&s.hdup[j0    ][wid][0]) = pack2(h0);
      *reinterpret_cast<u64*>(&s.hdup[j0 + 1][wid][0]) = pack2(h1);

      float part = h0 * s.W_d[j0] + h1 * s.W_d[j0 + 1];
      #pragma unroll
      for (int off = 16; off > 0; off >>= 1)
        part += __shfl_down_sync(0xffffffffu, part, off);
      if (lane == 0) out[(size_t)n * T + t] = part + bd;
    }
    __syncthreads();                               // S5
  }

  // ===== self-resetting barrier counter =====
  if (tid == 0) {
    const int ticket = atomicAdd(&g_bar, 1);
    if (ticket == NCTA * (T + 1) - 1) atomicExch(&g_bar, 0);
  }
}

extern "C" void kernel_launch(void* const* d_in, const int* in_sizes, int n_in,
                              void* d_out, int out_size) {
  const float* x    = (const float*)d_in[0];
  const float* A    = (const float*)d_in[1];
  const float* W_ih = (const float*)d_in[2];
  const float* W_hh = (const float*)d_in[3];
  const float* bias = (const float*)d_in[4];
  const float* W_q  = (const float*)d_in[5];
  const float* b_q  = (const float*)d_in[6];
  const float* W_d  = (const float*)d_in[7];
  const float* b_d  = (const float*)d_in[8];
  float* out = (float*)d_out;

  const int T = in_sizes[0] / (NN * DD);   // 365

  cudaFuncSetAttribute(rgcn_kernel, cudaFuncAttributeMaxDynamicSharedMemorySize,
                       (int)sizeof(Smem));
  rgcn_kernel<<<NCTA, NTH, sizeof(Smem)>>>(x, A, W_ih, W_hh, bias,
                                           W_q, b_q, W_d, b_d, out, T);
}

// round 16
// speedup vs baseline: 1.3299x; 1.2272x over previous
#include <cuda_runtime.h>
#include <cuda_bf16.h>
#include <cstdint>

#define NN   2048
#define DD   16
#define HH   64
#define G4   256
#define NCTA 128
#define ROWS 16
#define NTH  512
#define TKN  256          // nodes (k) per GEMM tile
#define NKT  (NN / TKN)   // 8 tiles
#define RP   72           // padded red row stride (floats): 2-way conflict floor

typedef unsigned long long u64;
typedef unsigned int u32;

// q in mma-B-fragment order, LANE-CONTIGUOUS slots:
//   slot index = c*4096 + w*256 + nc*32 + lane
//   content: lo u32 = {q[c*256+w*16+2(lane&3)][j], q[..+1][j]},
//            hi u32 = {q[c*256+w*16+8+2(lane&3)][j], q[..+1][j]},  j = nc*8 + (lane>>2)
__device__ u64 g_q64[2][NKT * 16 * 4 * HH];       // 2 x 256KB
__device__ uint4 g_Afb[(size_t)NCTA * 4096];      // A bf16 mma-fragment order (8MB)
__device__ int g_bar = 0;                         // grid barrier (self-resetting)

struct Smem {
  float red[16][16][RP];    // 73.7 KB  A@q k-split reduce (padded rows)
  float qred[4][16][64];    // 16 KB  q-phase k-split reduce
  float qfin[16][66];       // 4.1 KB final q (f32); 66-stride caps writer conflicts
  float gs[16][256];        // 16 KB  gate redistribution
  float W_ih[DD][G4];       // 16 KB
  float W_hh[HH][G4];       // 64 KB
  float W_q [HH][HH];       // 16 KB
  float bias[G4];
  float b_q [HH];
  float W_d [HH];
  float hdup[HH][18][2];    // h duplicated {h,h}, transposed (9.2KB)
  float xdup[DD][18][2];    // x_t duplicated, transposed
};

__device__ __forceinline__ u32 bfpack(float lo, float hi) {   // {hi<<16 | lo}
  u32 r; asm("cvt.rn.bf16x2.f32 %0, %1, %2;" : "=r"(r) : "f"(hi), "f"(lo)); return r;
}
__device__ __forceinline__ void mma16(float* c, uint4 a, u32 b0, u32 b1) {
  asm volatile("mma.sync.aligned.m16n8k16.row.col.f32.bf16.bf16.f32 "
               "{%0,%1,%2,%3}, {%4,%5,%6,%7}, {%8,%9}, {%0,%1,%2,%3};"
               : "+f"(c[0]), "+f"(c[1]), "+f"(c[2]), "+f"(c[3])
               : "r"(a.x), "r"(a.y), "r"(a.z), "r"(a.w), "r"(b0), "r"(b1));
}
__device__ __forceinline__ void fma2(u64& d, u64 a, u64 b) {
  asm("fma.rn.f32x2 %0, %1, %2, %0;" : "+l"(d) : "l"(a), "l"(b));
}
__device__ __forceinline__ u64 pack2(float v) {
  u64 r; asm("mov.b64 %0, {%1, %1};" : "=l"(r) : "f"(v)); return r;
}
__device__ __forceinline__ float sigm_f(float x) { return 1.0f / (1.0f + __expf(-x)); }
__device__ __forceinline__ float tanh_f(float x) { return 1.0f - 2.0f / (__expf(2.0f * x) + 1.0f); }

__global__ void __launch_bounds__(NTH, 1)
rgcn_kernel(const float* __restrict__ x,    const float* __restrict__ A,
            const float* __restrict__ W_ih, const float* __restrict__ W_hh,
            const float* __restrict__ bias, const float* __restrict__ W_q,
            const float* __restrict__ b_q,  const float* __restrict__ W_d,
            const float* __restrict__ b_d,  float* __restrict__ out, int T)
{
  extern __shared__ unsigned char smem_raw[];
  Smem& s = *reinterpret_cast<Smem*>(smem_raw);

  const int tid = threadIdx.x, wid = tid >> 5, lane = tid & 31;
  const int n_base = blockIdx.x * ROWS;
  const int n   = n_base + wid;             // this warp's node row
  const int j0  = 2 * lane;
  const int rw4 = (wid >> 2) * 4;           // gates/q: 4-row group base
  const int cw  = wid & 3;                  // gates: 64-col block | q: k-slice
  const int gc0 = cw * 64 + j0;

  // ---- weights into shared ----
  for (int i = tid; i < DD * G4; i += NTH) (&s.W_ih[0][0])[i] = W_ih[i];
  for (int i = tid; i < HH * G4; i += NTH) (&s.W_hh[0][0])[i] = W_hh[i];
  for (int i = tid; i < HH * HH; i += NTH) (&s.W_q[0][0])[i]  = W_q[i];
  for (int i = tid; i < G4;      i += NTH) s.bias[i] = bias[i];
  for (int i = tid; i < HH;      i += NTH) { s.b_q[i] = b_q[i]; s.W_d[i] = W_d[i]; }
  for (int i = tid; i < HH * 18 * 2; i += NTH) (&s.hdup[0][0][0])[i] = 0.0f;

  // ---- one-time: pack this CTA's A rows into bf16 mma-fragment order ----
  for (int i = tid; i < 4096; i += NTH) {
    const int tile = i >> 9, w = (i >> 5) & 15, ln = i & 31;
    const int k0 = tile * TKN + (w << 4) + ((ln & 3) << 1);
    const int r = ln >> 2;
    const float* r0 = A + (size_t)(n_base + r) * NN;
    const float* r8 = A + (size_t)(n_base + r + 8) * NN;
    uint4 v;
    v.x = bfpack(__ldg(r0 + k0),     __ldg(r0 + k0 + 1));
    v.y = bfpack(__ldg(r8 + k0),     __ldg(r8 + k0 + 1));
    v.z = bfpack(__ldg(r0 + k0 + 8), __ldg(r0 + k0 + 9));
    v.w = bfpack(__ldg(r8 + k0 + 8), __ldg(r8 + k0 + 9));
    g_Afb[(size_t)blockIdx.x * 4096 + i] = v;
  }
  __syncthreads();
  const float bd = __ldg(b_d);
  const uint4* fragbase = g_Afb + (size_t)blockIdx.x * 4096 + wid * 32 + lane;

  // q publish: thread tid<256 owns slot blk*256 + tid (fully coalesced STG.64)
  u64* qdst0 = &g_q64[0][(size_t)blockIdx.x * 256 + tid];
  u64* qdst1 = &g_q64[1][(size_t)blockIdx.x * 256 + tid];
  const int pj  = (tid >> 5) * 8 + ((tid & 31) >> 2);  // j this writer packs
  const int pr2 = ((tid & 3) << 1);                    // local node pair base

  // GEMM B-fragment base: contiguous per chunk (warp wid = k-slice)
  const int bbase0 = wid * 256 + lane;

  float c0r = 0.0f, c1r = 0.0f;    // cell state in registers

  for (int t = 0; t < T; ++t) {
    const int p = t & 1;

    // ===== stage x_t into duplicated-transposed smem =====
    if (tid < 256) {
      const int r = tid >> 4, d = tid & 15;
      const float xv = __ldg(&x[((size_t)(n_base + r) * T + t) * DD + d]);
      *reinterpret_cast<u64*>(&s.xdup[d][r][0]) = pack2(xv);
    }

    // ===== phase 1: q = tanh(h @ W_q + b_q); warp=(4 rows, k-slice cw*16) =====
    {
      u64 qacc[4] = {0ull, 0ull, 0ull, 0ull};
      #pragma unroll
      for (int kk = 0; kk < 16; ++kk) {
        const int k = (cw << 4) + kk;
        const u64 w2 = *reinterpret_cast<const u64*>(&s.W_q[k][j0]);
        const ulonglong2 h01 = *reinterpret_cast<const ulonglong2*>(&s.hdup[k][rw4][0]);
        const ulonglong2 h23 = *reinterpret_cast<const ulonglong2*>(&s.hdup[k][rw4 + 2][0]);
        fma2(qacc[0], h01.x, w2); fma2(qacc[1], h01.y, w2);
        fma2(qacc[2], h23.x, w2); fma2(qacc[3], h23.y, w2);
      }
      #pragma unroll
      for (int rr = 0; rr < 4; ++rr)
        *reinterpret_cast<u64*>(&s.qred[cw][rw4 + rr][j0]) = qacc[rr];
    }
    __syncthreads();                               // S1
    {
      float2 qs = make_float2(s.b_q[j0], s.b_q[j0 + 1]);
      #pragma unroll
      for (int kq = 0; kq < 4; ++kq) {
        const float2 v = *reinterpret_cast<const float2*>(&s.qred[kq][wid][j0]);
        qs.x += v.x; qs.y += v.y;
      }
      s.qfin[wid][j0]     = tanh_f(qs.x);
      s.qfin[wid][j0 + 1] = tanh_f(qs.y);
    }
    __syncthreads();                               // S1b
    // ===== publish q: lane-contiguous u64 fragment slots =====
    if (tid < 256) {
      const u32 lo = bfpack(s.qfin[pr2    ][pj], s.qfin[pr2 + 1][pj]);
      const u32 hi = bfpack(s.qfin[pr2 + 8][pj], s.qfin[pr2 + 9][pj]);
      *(p ? qdst1 : qdst0) = (u64)lo | ((u64)hi << 32);
      __threadfence();             // only the storing warps pay the membar
    }

    // ===== barrier ARRIVE (release q writes) =====
    __syncthreads();                               // S2
    if (tid == 0) atomicAdd(&g_bar, 1);

    // ===== gates: warp=(4 rows rw4.., 64-col block cw); overlaps barrier skew =====
    {
      u64 accg[4];
      const u64 b2 = *reinterpret_cast<const u64*>(&s.bias[gc0]);
      accg[0] = b2; accg[1] = b2; accg[2] = b2; accg[3] = b2;
      #pragma unroll
      for (int d = 0; d < DD; ++d) {
        const u64 w2 = *reinterpret_cast<const u64*>(&s.W_ih[d][gc0]);
        const ulonglong2 x01 = *reinterpret_cast<const ulonglong2*>(&s.xdup[d][rw4][0]);
        const ulonglong2 x23 = *reinterpret_cast<const ulonglong2*>(&s.xdup[d][rw4 + 2][0]);
        fma2(accg[0], x01.x, w2); fma2(accg[1], x01.y, w2);
        fma2(accg[2], x23.x, w2); fma2(accg[3], x23.y, w2);
      }
      #pragma unroll 8
      for (int k = 0; k < HH; ++k) {
        const u64 w2 = *reinterpret_cast<const u64*>(&s.W_hh[k][gc0]);
        const ulonglong2 h01 = *reinterpret_cast<const ulonglong2*>(&s.hdup[k][rw4][0]);
        const ulonglong2 h23 = *reinterpret_cast<const ulonglong2*>(&s.hdup[k][rw4 + 2][0]);
        fma2(accg[0], h01.x, w2); fma2(accg[1], h01.y, w2);
        fma2(accg[2], h23.x, w2); fma2(accg[3], h23.y, w2);
      }
      #pragma unroll
      for (int rr = 0; rr < 4; ++rr)
        *reinterpret_cast<u64*>(&s.gs[rw4 + rr][gc0]) = accg[rr];
    }

    // prefetch A-fragments for tiles 0/1 (constant data; hides behind spin)
    uint4 fr0 = __ldg(fragbase);
    uint4 fr1 = __ldg(fragbase + 512);

    // ===== barrier WAIT (acquire all q) =====
    if (tid == 0) {
      const int target = NCTA * (t + 1);
      while (*((volatile int*)&g_bar) < target) { }
    }
    __syncthreads();                               // S3

    // ===== phase 2: D[16x64] = A_rows @ q, bf16 mma, reg-double-buffered =====
    float acc[32];
    #pragma unroll
    for (int i = 0; i < 32; ++i) acc[i] = 0.0f;

    const u64* qb64 = &g_q64[p][0];
    u64 br0[8], br1[8];
    {
      const u64* bp0 = qb64 + bbase0;
      const u64* bp1 = qb64 + 4096 + bbase0;
      #pragma unroll
      for (int nc = 0; nc < 8; ++nc) br0[nc] = __ldcg(bp0 + nc * 32);
      #pragma unroll
      for (int nc = 0; nc < 8; ++nc) br1[nc] = __ldcg(bp1 + nc * 32);
    }

    #pragma unroll 1
    for (int cc = 0; cc < NKT / 2; ++cc) {
      // --- even tile c = 2cc ---
      {
        u64 cur[8];
        #pragma unroll
        for (int nc = 0; nc < 8; ++nc) cur[nc] = br0[nc];
        const uint4 cf = fr0;
        if (cc < NKT / 2 - 1) {                    // prefetch tile 2cc+2
          const u64* bp = qb64 + (size_t)(2 * cc + 2) * 4096 + bbase0;
          #pragma unroll
          for (int nc = 0; nc < 8; ++nc) br0[nc] = __ldcg(bp + nc * 32);
          fr0 = __ldg(fragbase + (2 * cc + 2) * 512);
        }
        #pragma unroll
        for (int nc = 0; nc < 8; ++nc)
          mma16(acc + nc * 4, cf, (u32)(cur[nc] & 0xffffffffull), (u32)(cur[nc] >> 32));
      }
      // --- odd tile c = 2cc+1 ---
      {
        u64 cur[8];
        #pragma unroll
        for (int nc = 0; nc < 8; ++nc) cur[nc] = br1[nc];
        const uint4 cf = fr1;
        if (cc < NKT / 2 - 1) {                    // prefetch tile 2cc+3
          const u64* bp = qb64 + (size_t)(2 * cc + 3) * 4096 + bbase0;
          #pragma unroll
          for (int nc = 0; nc < 8; ++nc) br1[nc] = __ldcg(bp + nc * 32);
          fr1 = __ldg(fragbase + (2 * cc + 3) * 512);
        }
        #pragma unroll
        for (int nc = 0; nc < 8; ++nc)
          mma16(acc + nc * 4, cf, (u32)(cur[nc] & 0xffffffffull), (u32)(cur[nc] >> 32));
      }
    }

    // ===== reduce A@q k-split partials via smem (padded rows: 2-way max) =====
    {
      const int r = lane >> 2, cc2 = (lane & 3) * 2;
      #pragma unroll
      for (int nc = 0; nc < 8; ++nc) {
        *reinterpret_cast<float2*>(&s.red[wid][r][nc * 8 + cc2]) =
            make_float2(acc[nc * 4 + 0], acc[nc * 4 + 1]);
        *reinterpret_cast<float2*>(&s.red[wid][r + 8][nc * 8 + cc2]) =
            make_float2(acc[nc * 4 + 2], acc[nc * 4 + 3]);
      }
    }
    __syncthreads();                               // S4
    float2 aqv = make_float2(0.0f, 0.0f);
    #pragma unroll
    for (int w2 = 0; w2 < 16; ++w2) {
      const float2 v = *reinterpret_cast<const float2*>(&s.red[w2][wid][j0]);
      aqv.x += v.x; aqv.y += v.y;
    }

    // ===== activations + state update (warp wid owns row wid) =====
    {
      const float2 gi = *reinterpret_cast<const float2*>(&s.gs[wid][  0 + j0]);
      const float2 gf = *reinterpret_cast<const float2*>(&s.gs[wid][ 64 + j0]);
      const float2 gg = *reinterpret_cast<const float2*>(&s.gs[wid][128 + j0]);
      const float2 go = *reinterpret_cast<const float2*>(&s.gs[wid][192 + j0]);

      const float i0 = sigm_f(gi.x), i1 = sigm_f(gi.y);
      const float f0 = sigm_f(gf.x), f1 = sigm_f(gf.y);
      const float g0 = tanh_f(gg.x), g1 = tanh_f(gg.y);
      const float o0 = sigm_f(go.x), o1 = sigm_f(go.y);

      c0r = f0 * (c0r + aqv.x) + i0 * g0;
      c1r = f1 * (c1r + aqv.y) + i1 * g1;
      const float h0 = o0 * tanh_f(c0r);
      const float h1 = o1 * tanh_f(c1r);

      *reinterpret_cast<u64*>(&s.hdup[j0    ][wid][0]) = pack2(h0);
      *reinterpret_cast<u64*>(&s.hdup[j0 + 1][wid][0]) = pack2(h1);

      float part = h0 * s.W_d[j0] + h1 * s.W_d[j0 + 1];
      #pragma unroll
      for (int off = 16; off > 0; off >>= 1)
        part += __shfl_down_sync(0xffffffffu, part, off);
      if (lane == 0) out[(size_t)n * T + t] = part + bd;
    }
    __syncthreads();                               // S5
  }

  // ===== self-resetting barrier counter =====
  if (tid == 0) {
    const int ticket = atomicAdd(&g_bar, 1);
    if (ticket == NCTA * (T + 1) - 1) atomicExch(&g_bar, 0);
  }
}

extern "C" void kernel_launch(void* const* d_in, const int* in_sizes, int n_in,
                              void* d_out, int out_size) {
  const float* x    = (const float*)d_in[0];
  const float* A    = (const float*)d_in[1];
  const float* W_ih = (const float*)d_in[2];
  const float* W_hh = (const float*)d_in[3];
  const float* bias = (const float*)d_in[4];
  const float* W_q  = (const float*)d_in[5];
  const float* b_q  = (const float*)d_in[6];
  const float* W_d  = (const float*)d_in[7];
  const float* b_d  = (const float*)d_in[8];
  float* out = (float*)d_out;

  const int T = in_sizes[0] / (NN * DD);   // 365

  cudaFuncSetAttribute(rgcn_kernel, cudaFuncAttributeMaxDynamicSharedMemorySize,
                       (int)sizeof(Smem));
  rgcn_kernel<<<NCTA, NTH, sizeof(Smem)>>>(x, A, W_ih, W_hh, bias,
                                           W_q, b_q, W_d, b_d, out, T);
}